// round 2
// baseline (speedup 1.0000x reference)
#include <cuda_runtime.h>
#include <cstdint>

// Problem constants
#define B_    8
#define CIN   256
#define T_    16000
#define COUT  512
#define KW    3
#define WPC   8           // u32 words per (b,t): CIN/32
#define NW    24          // words per output channel: KW*WPC
#define NPART 1000        // partial sums per batch for beta (8 w-groups * 125 t-chunks)

// Scratch (no allocations allowed) -------------------------------------------
__device__ unsigned xpack_g[B_ * WPC * T_];   // [b][w][t]  bit c%32 = (x>=0)
__device__ unsigned wpack_g[COUT * NW];       // [co][k*8+w]
__device__ float    alpha_g[COUT];
__device__ float    beta_g[B_];
__device__ float    partial_g[B_ * NPART];

// ----------------------------------------------------------------------------
// Kernel 1: pack sign bits of x (coalesced along t) + per-block |x| partials
// grid (125, 8, 8) = (t-chunk, w, b), 128 threads
// ----------------------------------------------------------------------------
__global__ __launch_bounds__(128) void pack_x_kernel(const float* __restrict__ x) {
    const int tc = blockIdx.x, w = blockIdx.y, b = blockIdx.z;
    const int tid = threadIdx.x;
    const int t = tc * 128 + tid;

    const float* p = x + ((size_t)(b * CIN + w * 32)) * T_ + t;
    unsigned word = 0;
    float s = 0.f;
#pragma unroll
    for (int c = 0; c < 32; c++) {
        float v = p[(size_t)c * T_];               // coalesced across lanes
        word |= (v >= 0.f ? 1u : 0u) << c;
        s += fabsf(v);
    }
    xpack_g[(b * WPC + w) * T_ + t] = word;

    __shared__ float red[128];
    red[tid] = s;
    __syncthreads();
#pragma unroll
    for (int off = 64; off > 0; off >>= 1) {
        if (tid < off) red[tid] += red[tid + off];
        __syncthreads();
    }
    if (tid == 0) partial_g[b * NPART + w * 125 + tc] = red[0];
}

// ----------------------------------------------------------------------------
// Kernel 2: pack weight sign bits + alpha[co].  512 threads total.
// ----------------------------------------------------------------------------
__global__ __launch_bounds__(256) void pack_w_kernel(const float* __restrict__ wt) {
    const int co = blockIdx.x * 256 + threadIdx.x;
    unsigned words[NW];
#pragma unroll
    for (int i = 0; i < NW; i++) words[i] = 0;
    float s = 0.f;
    const float* p = wt + (size_t)co * CIN * KW;
    for (int c = 0; c < CIN; c++) {
#pragma unroll
        for (int k = 0; k < KW; k++) {
            float v = p[c * KW + k];
            s += fabsf(v);
            words[k * 8 + (c >> 5)] |= (v >= 0.f ? 1u : 0u) << (c & 31);
        }
    }
#pragma unroll
    for (int i = 0; i < NW; i++) wpack_g[co * NW + i] = words[i];
    alpha_g[co] = s * (1.0f / (CIN * KW));
}

// ----------------------------------------------------------------------------
// Kernel 3: deterministic beta reduction.  grid 8, 256 threads.
// ----------------------------------------------------------------------------
__global__ __launch_bounds__(256) void beta_kernel() {
    const int b = blockIdx.x, tid = threadIdx.x;
    float s = 0.f;
    for (int i = tid; i < NPART; i += 256) s += partial_g[b * NPART + i];
    __shared__ float red[256];
    red[tid] = s;
    __syncthreads();
#pragma unroll
    for (int off = 128; off > 0; off >>= 1) {
        if (tid < off) red[tid] += red[tid + off];
        __syncthreads();
    }
    if (tid == 0) beta_g[b] = red[0] * (1.0f / ((float)CIN * (float)T_));
}

// ----------------------------------------------------------------------------
// Kernel 4: main XNOR-popcount conv.
// grid (125, 8) = (t-chunk of 128, b), 256 threads:
//   t_local = tid & 127, co_half = tid >> 7 (each half does 256 output chans).
// x words for taps t-1, t, t+1 live in registers across the whole co loop;
// packed weights live in SMEM (warp-uniform broadcast LDS.128, conflict-free).
// dot = 256*n_valid_taps - 2 * sum(popc(x ^ w)); edges handled by masks.
//
// NOTE (round-2 fork, decided by ncu): if POPC shows rt_SMSP≈8 (quarter-rate),
// switch the inner body to a CSA tree (24 POPC -> 6 POPC, +36 LOP3); if the
// kernel is POPC-bound even then, move to int8 tcgen05 implicit GEMM.
// ----------------------------------------------------------------------------
__global__ __launch_bounds__(256) void conv_kernel(float* __restrict__ out) {
    __shared__ unsigned wsm[COUT * NW];               // 49152 B = 48 KB exactly

    const int tid = threadIdx.x;
    const int tl = tid & 127;
    const int co0 = (tid >> 7) * 256;
    const int b = blockIdx.y;
    const int t = blockIdx.x * 128 + tl;

    // cooperative SMEM fill (48 loads/thread, coalesced)
    for (int i = tid; i < COUT * NW; i += 256) wsm[i] = wpack_g[i];

    const unsigned* xp = xpack_g + (size_t)b * WPC * T_;
    const int tm = (t > 0) ? t - 1 : 0;
    const int tp = (t < T_ - 1) ? t + 1 : t;

    unsigned x0[8], x1[8], x2[8];
#pragma unroll
    for (int w = 0; w < 8; w++) {
        x0[w] = xp[w * T_ + tm];
        x1[w] = xp[w * T_ + t];
        x2[w] = xp[w * T_ + tp];
    }
    const int mask0 = (t > 0) ? -1 : 0;
    const int mask2 = (t < T_ - 1) ? -1 : 0;
    const int base = 256 * (1 + (t > 0) + (t < T_ - 1));
    const float beta = beta_g[b];

    __syncthreads();

    float* op = out + (size_t)b * COUT * T_ + t;

#pragma unroll 2
    for (int c = 0; c < 256; c++) {
        const int co = co0 + c;
        const uint4* wr = reinterpret_cast<const uint4*>(&wsm[co * NW]);
        uint4 a0 = wr[0], a1 = wr[1], a2 = wr[2], a3 = wr[3], a4 = wr[4], a5 = wr[5];

        int m0 = ((__popc(x0[0] ^ a0.x) + __popc(x0[1] ^ a0.y)) +
                  (__popc(x0[2] ^ a0.z) + __popc(x0[3] ^ a0.w))) +
                 ((__popc(x0[4] ^ a1.x) + __popc(x0[5] ^ a1.y)) +
                  (__popc(x0[6] ^ a1.z) + __popc(x0[7] ^ a1.w)));
        int m1 = ((__popc(x1[0] ^ a2.x) + __popc(x1[1] ^ a2.y)) +
                  (__popc(x1[2] ^ a2.z) + __popc(x1[3] ^ a2.w))) +
                 ((__popc(x1[4] ^ a3.x) + __popc(x1[5] ^ a3.y)) +
                  (__popc(x1[6] ^ a3.z) + __popc(x1[7] ^ a3.w)));
        int m2 = ((__popc(x2[0] ^ a4.x) + __popc(x2[1] ^ a4.y)) +
                  (__popc(x2[2] ^ a4.z) + __popc(x2[3] ^ a4.w))) +
                 ((__popc(x2[4] ^ a5.x) + __popc(x2[5] ^ a5.y)) +
                  (__popc(x2[6] ^ a5.z) + __popc(x2[7] ^ a5.w)));

        const int m = (m0 & mask0) + m1 + (m2 & mask2);
        const float alpha = __ldg(&alpha_g[co]);
        const float r = (float)(base - 2 * m) * (alpha * beta);
        op[(size_t)co * T_] = r;                       // 128B full-line stores/warp
    }
}

// ----------------------------------------------------------------------------
extern "C" void kernel_launch(void* const* d_in, const int* in_sizes, int n_in,
                              void* d_out, int out_size) {
    const float* x  = (const float*)d_in[0];   // [8,256,16000] f32
    const float* wt = (const float*)d_in[1];   // [512,256,3]   f32
    float* out = (float*)d_out;                // [8,512,16000] f32

    pack_x_kernel<<<dim3(125, 8, 8), 128>>>(x);
    pack_w_kernel<<<2, 256>>>(wt);
    beta_kernel<<<8, 256>>>();
    conv_kernel<<<dim3(125, 8), 256>>>(out);
}

// round 3
// speedup vs baseline: 1.0009x; 1.0009x over previous
#include <cuda_runtime.h>
#include <cstdint>

// Problem constants
#define B_    8
#define CIN   256
#define T_    16000
#define COUT  512
#define KW    3
#define WPC   8           // u32 words per (b,t): CIN/32
#define NW    24          // words per output channel: KW*WPC
#define NPART 1000        // partial sums per batch for beta (8 w-groups * 125 t-chunks)

// Scratch (no allocations allowed) -------------------------------------------
__device__ unsigned xpack_g[B_ * WPC * T_];   // [b][w][t]  bit c%32 = (x>=0)
__device__ unsigned wpack_g[COUT * NW];       // [co][k*8+w]
__device__ float    alpha_g[COUT];
__device__ float    beta_g[B_];
__device__ float    partial_g[B_ * NPART];

// ----------------------------------------------------------------------------
// Kernel 1: pack sign bits of x (coalesced along t) + per-block |x| partials
// grid (125, 8, 8) = (t-chunk, w, b), 128 threads
// ----------------------------------------------------------------------------
__global__ __launch_bounds__(128) void pack_x_kernel(const float* __restrict__ x) {
    const int tc = blockIdx.x, w = blockIdx.y, b = blockIdx.z;
    const int tid = threadIdx.x;
    const int t = tc * 128 + tid;

    const float* p = x + ((size_t)(b * CIN + w * 32)) * T_ + t;
    unsigned word = 0;
    float s = 0.f;
#pragma unroll
    for (int c = 0; c < 32; c++) {
        float v = p[(size_t)c * T_];               // coalesced across lanes
        word |= (v >= 0.f ? 1u : 0u) << c;
        s += fabsf(v);
    }
    xpack_g[(b * WPC + w) * T_ + t] = word;

    __shared__ float red[128];
    red[tid] = s;
    __syncthreads();
#pragma unroll
    for (int off = 64; off > 0; off >>= 1) {
        if (tid < off) red[tid] += red[tid + off];
        __syncthreads();
    }
    if (tid == 0) partial_g[b * NPART + w * 125 + tc] = red[0];
}

// ----------------------------------------------------------------------------
// Kernel 2: pack weight sign bits + alpha[co].  512 threads total.
// ----------------------------------------------------------------------------
__global__ __launch_bounds__(256) void pack_w_kernel(const float* __restrict__ wt) {
    const int co = blockIdx.x * 256 + threadIdx.x;
    unsigned words[NW];
#pragma unroll
    for (int i = 0; i < NW; i++) words[i] = 0;
    float s = 0.f;
    const float* p = wt + (size_t)co * CIN * KW;
    for (int c = 0; c < CIN; c++) {
#pragma unroll
        for (int k = 0; k < KW; k++) {
            float v = p[c * KW + k];
            s += fabsf(v);
            words[k * 8 + (c >> 5)] |= (v >= 0.f ? 1u : 0u) << (c & 31);
        }
    }
#pragma unroll
    for (int i = 0; i < NW; i++) wpack_g[co * NW + i] = words[i];
    alpha_g[co] = s * (1.0f / (CIN * KW));
}

// ----------------------------------------------------------------------------
// Kernel 3: deterministic beta reduction.  grid 8, 256 threads.
// ----------------------------------------------------------------------------
__global__ __launch_bounds__(256) void beta_kernel() {
    const int b = blockIdx.x, tid = threadIdx.x;
    float s = 0.f;
    for (int i = tid; i < NPART; i += 256) s += partial_g[b * NPART + i];
    __shared__ float red[256];
    red[tid] = s;
    __syncthreads();
#pragma unroll
    for (int off = 128; off > 0; off >>= 1) {
        if (tid < off) red[tid] += red[tid + off];
        __syncthreads();
    }
    if (tid == 0) beta_g[b] = red[0] * (1.0f / ((float)CIN * (float)T_));
}

// ----------------------------------------------------------------------------
// Kernel 4: main XNOR-popcount conv.
// grid (125, 8) = (t-chunk of 128, b), 256 threads:
//   t_local = tid & 127, co_half = tid >> 7 (each half does 256 output chans).
// x words for taps t-1, t, t+1 live in registers across the whole co loop;
// packed weights live in SMEM (warp-uniform broadcast LDS.128, conflict-free).
// dot = 256*n_valid_taps - 2 * sum(popc(x ^ w)); edges handled by masks.
//
// NOTE (round-2 fork, decided by ncu): if POPC shows rt_SMSP≈8 (quarter-rate),
// switch the inner body to a CSA tree (24 POPC -> 6 POPC, +36 LOP3); if the
// kernel is POPC-bound even then, move to int8 tcgen05 implicit GEMM.
// ----------------------------------------------------------------------------
__global__ __launch_bounds__(256) void conv_kernel(float* __restrict__ out) {
    __shared__ unsigned wsm[COUT * NW];               // 49152 B = 48 KB exactly

    const int tid = threadIdx.x;
    const int tl = tid & 127;
    const int co0 = (tid >> 7) * 256;
    const int b = blockIdx.y;
    const int t = blockIdx.x * 128 + tl;

    // cooperative SMEM fill (48 loads/thread, coalesced)
    for (int i = tid; i < COUT * NW; i += 256) wsm[i] = wpack_g[i];

    const unsigned* xp = xpack_g + (size_t)b * WPC * T_;
    const int tm = (t > 0) ? t - 1 : 0;
    const int tp = (t < T_ - 1) ? t + 1 : t;

    unsigned x0[8], x1[8], x2[8];
#pragma unroll
    for (int w = 0; w < 8; w++) {
        x0[w] = xp[w * T_ + tm];
        x1[w] = xp[w * T_ + t];
        x2[w] = xp[w * T_ + tp];
    }
    const int mask0 = (t > 0) ? -1 : 0;
    const int mask2 = (t < T_ - 1) ? -1 : 0;
    const int base = 256 * (1 + (t > 0) + (t < T_ - 1));
    const float beta = beta_g[b];

    __syncthreads();

    float* op = out + (size_t)b * COUT * T_ + t;

#pragma unroll 2
    for (int c = 0; c < 256; c++) {
        const int co = co0 + c;
        const uint4* wr = reinterpret_cast<const uint4*>(&wsm[co * NW]);
        uint4 a0 = wr[0], a1 = wr[1], a2 = wr[2], a3 = wr[3], a4 = wr[4], a5 = wr[5];

        int m0 = ((__popc(x0[0] ^ a0.x) + __popc(x0[1] ^ a0.y)) +
                  (__popc(x0[2] ^ a0.z) + __popc(x0[3] ^ a0.w))) +
                 ((__popc(x0[4] ^ a1.x) + __popc(x0[5] ^ a1.y)) +
                  (__popc(x0[6] ^ a1.z) + __popc(x0[7] ^ a1.w)));
        int m1 = ((__popc(x1[0] ^ a2.x) + __popc(x1[1] ^ a2.y)) +
                  (__popc(x1[2] ^ a2.z) + __popc(x1[3] ^ a2.w))) +
                 ((__popc(x1[4] ^ a3.x) + __popc(x1[5] ^ a3.y)) +
                  (__popc(x1[6] ^ a3.z) + __popc(x1[7] ^ a3.w)));
        int m2 = ((__popc(x2[0] ^ a4.x) + __popc(x2[1] ^ a4.y)) +
                  (__popc(x2[2] ^ a4.z) + __popc(x2[3] ^ a4.w))) +
                 ((__popc(x2[4] ^ a5.x) + __popc(x2[5] ^ a5.y)) +
                  (__popc(x2[6] ^ a5.z) + __popc(x2[7] ^ a5.w)));

        const int m = (m0 & mask0) + m1 + (m2 & mask2);
        const float alpha = __ldg(&alpha_g[co]);
        const float r = (float)(base - 2 * m) * (alpha * beta);
        op[(size_t)co * T_] = r;                       // 128B full-line stores/warp
    }
}

// ----------------------------------------------------------------------------
extern "C" void kernel_launch(void* const* d_in, const int* in_sizes, int n_in,
                              void* d_out, int out_size) {
    const float* x  = (const float*)d_in[0];   // [8,256,16000] f32
    const float* wt = (const float*)d_in[1];   // [512,256,3]   f32
    float* out = (float*)d_out;                // [8,512,16000] f32

    pack_x_kernel<<<dim3(125, 8, 8), 128>>>(x);
    pack_w_kernel<<<2, 256>>>(wt);
    beta_kernel<<<8, 256>>>();
    conv_kernel<<<dim3(125, 8), 256>>>(out);
}